// round 2
// baseline (speedup 1.0000x reference)
#include <cuda_runtime.h>
#include <cuda_bf16.h>

// Problem constants (fixed shapes from reference):
//   x:    (4, 64, 512, 512) fp32
//   iperm:(4, 4) int32
//   out:  (4, 64, 256, 256) fp32
//
// out[b, n*4+k, h, w] = sum_g x[b, g*16+n, 2h + pos/2, 2w + pos%2], pos = iperm[g*4+k]
//
// Per-thread tile: 4 output columns (w = 4*w4 .. 4*w4+3) for all 4 k values.
// Per g: reads 8 consecutive floats from rows 2h and 2h+1 (2x float4 each, __ldcs).
// Stores: 4x float4 streaming stores (__stcs), fully coalesced (512B/warp/instr).

__global__ void __launch_bounds__(256, 8)
muxout_transpose_kernel(const float* __restrict__ x,
                        const int*   __restrict__ iperm,
                        float*       __restrict__ out) {
    __shared__ int sp[16];
    if (threadIdx.x < 16) sp[threadIdx.x] = iperm[threadIdx.x];
    __syncthreads();

    // Total threads: B(4) * Ng(16) * H(256) * W/4(64) = 1,048,576 -> 4096 blocks
    const unsigned t  = blockIdx.x * 256u + threadIdx.x;
    const int w4 = t & 63;           // output w base = 4*w4; input col base = 8*w4
    const int h  = (t >> 6) & 255;   // 0..255
    const int n  = (t >> 14) & 15;   // 0..15
    const int b  = t >> 18;          // 0..3

    float acc[4][4];
    #pragma unroll
    for (int k = 0; k < 4; k++)
        #pragma unroll
        for (int j = 0; j < 4; j++)
            acc[k][j] = 0.0f;

    #pragma unroll
    for (int g = 0; g < 4; g++) {
        const size_t chan = (size_t)(b * 64 + g * 16 + n);
        const float4* row0 = reinterpret_cast<const float4*>(
            x + (chan * 512 + (size_t)(2 * h)) * 512) + 2 * w4;
        const float4* row1 = row0 + 128;  // next input row (+512 floats)
        const float4 r0a = __ldcs(row0);
        const float4 r0b = __ldcs(row0 + 1);
        const float4 r1a = __ldcs(row1);
        const float4 r1b = __ldcs(row1 + 1);

        // v[j][pos]: j = output column offset (0..3), pos = sh*2 + sw
        // input cols for j: 2j (sw=0), 2j+1 (sw=1); rows: 2h (sh=0), 2h+1 (sh=1)
        const float v[4][4] = {
            { r0a.x, r0a.y, r1a.x, r1a.y },
            { r0a.z, r0a.w, r1a.z, r1a.w },
            { r0b.x, r0b.y, r1b.x, r1b.y },
            { r0b.z, r0b.w, r1b.z, r1b.w },
        };

        #pragma unroll
        for (int k = 0; k < 4; k++) {
            const int pos = sp[g * 4 + k];
            const bool p1 = (pos & 1) != 0;
            const bool p2 = (pos & 2) != 0;
            #pragma unroll
            for (int j = 0; j < 4; j++) {
                const float a = p1 ? v[j][1] : v[j][0];
                const float c = p1 ? v[j][3] : v[j][2];
                acc[k][j] += p2 ? c : a;
            }
        }
    }

    const size_t out_base = (((size_t)(b * 64 + n * 4)) * 256 + h) * 256 + 4 * w4;

    #pragma unroll
    for (int k = 0; k < 4; k++) {
        float4 o;
        o.x = acc[k][0]; o.y = acc[k][1]; o.z = acc[k][2]; o.w = acc[k][3];
        __stcs(reinterpret_cast<float4*>(out + out_base + (size_t)k * (256 * 256)), o);
    }
}

extern "C" void kernel_launch(void* const* d_in, const int* in_sizes, int n_in,
                              void* d_out, int out_size) {
    const float* x     = (const float*)d_in[0];
    const int*   iperm = (const int*)d_in[1];
    float*       out   = (float*)d_out;

    muxout_transpose_kernel<<<4096, 256>>>(x, iperm, out);
}

// round 3
// speedup vs baseline: 1.1709x; 1.1709x over previous
#include <cuda_runtime.h>
#include <cuda_bf16.h>

// Problem constants (fixed shapes from reference):
//   x:    (4, 64, 512, 512) fp32
//   iperm:(4, 4) int32
//   out:  (4, 64, 256, 256) fp32
//
// out[b, n*4+k, h, w] = sum_g x[b, g*16+n, 2h + pos/2, 2w + pos%2], pos = iperm[g*4+k]
//
// R1 structure (2 output columns / thread, 8 live accumulators, fits 32 regs)
// + streaming cache hints on the single-use loads/stores.

__device__ __forceinline__ float sel4(float v0, float v1, float v2, float v3, int pos) {
    float a = (pos & 1) ? v1 : v0;   // pos in {0,1}
    float b = (pos & 1) ? v3 : v2;   // pos in {2,3}
    return (pos & 2) ? b : a;
}

__global__ void __launch_bounds__(256)
muxout_transpose_kernel(const float* __restrict__ x,
                        const int*   __restrict__ iperm,
                        float*       __restrict__ out) {
    __shared__ int sp[16];
    if (threadIdx.x < 16) sp[threadIdx.x] = iperm[threadIdx.x];
    __syncthreads();

    // Total threads: B(4) * Ng(16) * H(256) * W/2(128) = 2,097,152 -> 8192 blocks
    const unsigned t  = blockIdx.x * 256u + threadIdx.x;
    const int w2 = t & 127;          // 0..127  (covers output w = 2*w2, 2*w2+1)
    const int h  = (t >> 7) & 255;   // 0..255
    const int n  = (t >> 15) & 15;   // 0..15
    const int b  = t >> 19;          // 0..3

    float acc_lo[4] = {0.f, 0.f, 0.f, 0.f};
    float acc_hi[4] = {0.f, 0.f, 0.f, 0.f};

    #pragma unroll
    for (int g = 0; g < 4; g++) {
        const size_t chan = (size_t)(b * 64 + g * 16 + n);
        const float4* row0 = reinterpret_cast<const float4*>(
            x + (chan * 512 + (size_t)(2 * h)) * 512) + w2;
        const float4* row1 = row0 + 128;  // next input row (+512 floats)
        const float4 r0 = __ldcs(row0);
        const float4 r1 = __ldcs(row1);
        // pos = sh*2 + sw; lo = output col 2*w2, hi = 2*w2+1
        #pragma unroll
        for (int k = 0; k < 4; k++) {
            const int pos = sp[g * 4 + k];
            acc_lo[k] += sel4(r0.x, r0.y, r1.x, r1.y, pos);
            acc_hi[k] += sel4(r0.z, r0.w, r1.z, r1.w, pos);
        }
    }

    const size_t out_base = (((size_t)(b * 64 + n * 4)) * 256 + h) * 256 + 2 * w2;

    #pragma unroll
    for (int k = 0; k < 4; k++) {
        float2 o; o.x = acc_lo[k]; o.y = acc_hi[k];
        __stcs(reinterpret_cast<float2*>(out + out_base + (size_t)k * (256 * 256)), o);
    }
}

extern "C" void kernel_launch(void* const* d_in, const int* in_sizes, int n_in,
                              void* d_out, int out_size) {
    const float* x     = (const float*)d_in[0];
    const int*   iperm = (const int*)d_in[1];
    float*       out   = (float*)d_out;

    muxout_transpose_kernel<<<8192, 256>>>(x, iperm, out);
}

// round 4
// speedup vs baseline: 1.1972x; 1.0225x over previous
#include <cuda_runtime.h>
#include <cuda_bf16.h>

// Problem constants (fixed shapes from reference):
//   x:    (4, 64, 512, 512) fp32
//   iperm:(4, 4) int32
//   out:  (4, 64, 256, 256) fp32
//
// out[b, n*4+k, h, w] = sum_g x[b, g*16+n, 2h + pos/2, 2w + pos%2], pos = iperm[g*4+k]
//
// R1 structure (2 output columns / thread, 8 live accumulators, 32-reg cap,
// occ ~86%) + streaming cache hints (__ldcs/__stcs) on the single-use traffic.

__device__ __forceinline__ float sel4(float v0, float v1, float v2, float v3, int pos) {
    float a = (pos & 1) ? v1 : v0;   // pos in {0,1}
    float b = (pos & 1) ? v3 : v2;   // pos in {2,3}
    return (pos & 2) ? b : a;
}

__global__ void __launch_bounds__(256, 8)
muxout_transpose_kernel(const float* __restrict__ x,
                        const int*   __restrict__ iperm,
                        float*       __restrict__ out) {
    __shared__ int sp[16];
    if (threadIdx.x < 16) sp[threadIdx.x] = iperm[threadIdx.x];
    __syncthreads();

    // Total threads: B(4) * Ng(16) * H(256) * W/2(128) = 2,097,152 -> 8192 blocks
    const unsigned t  = blockIdx.x * 256u + threadIdx.x;
    const int w2 = t & 127;          // 0..127  (covers output w = 2*w2, 2*w2+1)
    const int h  = (t >> 7) & 255;   // 0..255
    const int n  = (t >> 15) & 15;   // 0..15
    const int b  = t >> 19;          // 0..3

    float acc_lo[4] = {0.f, 0.f, 0.f, 0.f};
    float acc_hi[4] = {0.f, 0.f, 0.f, 0.f};

    #pragma unroll
    for (int g = 0; g < 4; g++) {
        const size_t chan = (size_t)(b * 64 + g * 16 + n);
        const float4* row0 = reinterpret_cast<const float4*>(
            x + (chan * 512 + (size_t)(2 * h)) * 512) + w2;
        const float4* row1 = row0 + 128;  // next input row (+512 floats)
        const float4 r0 = __ldcs(row0);
        const float4 r1 = __ldcs(row1);
        // pos = sh*2 + sw; lo = output col 2*w2, hi = 2*w2+1
        #pragma unroll
        for (int k = 0; k < 4; k++) {
            const int pos = sp[g * 4 + k];
            acc_lo[k] += sel4(r0.x, r0.y, r1.x, r1.y, pos);
            acc_hi[k] += sel4(r0.z, r0.w, r1.z, r1.w, pos);
        }
    }

    const size_t out_base = (((size_t)(b * 64 + n * 4)) * 256 + h) * 256 + 2 * w2;

    #pragma unroll
    for (int k = 0; k < 4; k++) {
        float2 o; o.x = acc_lo[k]; o.y = acc_hi[k];
        __stcs(reinterpret_cast<float2*>(out + out_base + (size_t)k * (256 * 256)), o);
    }
}

extern "C" void kernel_launch(void* const* d_in, const int* in_sizes, int n_in,
                              void* d_out, int out_size) {
    const float* x     = (const float*)d_in[0];
    const int*   iperm = (const int*)d_in[1];
    float*       out   = (float*)d_out;

    muxout_transpose_kernel<<<8192, 256>>>(x, iperm, out);
}